// round 1
// baseline (speedup 1.0000x reference)
#include <cuda_runtime.h>
#include <cuda_bf16.h>

// RobustPrompt_I: graph prompt + edge pruning
//  in: x[N,128] f32, edge_index[2,E] i32, p_sim[1,128], p_deg[1,128], p_other[1,128]
//  out: x_new[N,128] f32  ++  keep[E] (0/1 as f32)

#define D        128
#define D4       32          // D/4 float4s per row
#define NCAP     131072
#define SIM_THR  0.2f
#define DEG_THR  3.0f
#define PT_THR   0.1f
#define EPSV     1e-8f

__device__ float g_csum[NCAP];   // per-node sum of edge cosines (scatter to col)
__device__ int   g_deg[NCAP];    // per-node degree (scatter to col)
__device__ float g_rinv[NCAP];   // 1/||x_i||
__device__ float g_rinv2[NCAP];  // 1/max(||x_new_i||, eps)
__device__ int   g_nz[3];        // all-nonzero flags for the 3 prompt rows

// ---------------------------------------------------------------- zero scratch
__global__ void zero_kernel(int n) {
    int i = blockIdx.x * blockDim.x + threadIdx.x;
    if (i < n) { g_csum[i] = 0.f; g_deg[i] = 0; }
}

// ------------------------------------------------- prompt all-nonzero flags (1 warp)
__global__ void flags_kernel(const float* __restrict__ ps,
                             const float* __restrict__ pd,
                             const float* __restrict__ po) {
    int lane = threadIdx.x;
    float4 a = reinterpret_cast<const float4*>(ps)[lane];
    float4 b = reinterpret_cast<const float4*>(pd)[lane];
    float4 c = reinterpret_cast<const float4*>(po)[lane];
    bool za = (a.x != 0.f) & (a.y != 0.f) & (a.z != 0.f) & (a.w != 0.f);
    bool zb = (b.x != 0.f) & (b.y != 0.f) & (b.z != 0.f) & (b.w != 0.f);
    bool zc = (c.x != 0.f) & (c.y != 0.f) & (c.z != 0.f) & (c.w != 0.f);
    unsigned full = 0xFFFFFFFFu;
    int fa = __all_sync(full, za);
    int fb = __all_sync(full, zb);
    int fc = __all_sync(full, zc);
    if (lane == 0) { g_nz[0] = fa; g_nz[1] = fb; g_nz[2] = fc; }
}

// --------------------------------------------------- per-node 1/||x|| (warp/node)
__global__ void norm_kernel(const float* __restrict__ x, int n) {
    int w    = (blockIdx.x * blockDim.x + threadIdx.x) >> 5;
    int lane = threadIdx.x & 31;
    if (w >= n) return;
    float4 a = reinterpret_cast<const float4*>(x)[w * D4 + lane];
    float s = a.x * a.x + a.y * a.y + a.z * a.z + a.w * a.w;
    #pragma unroll
    for (int o = 16; o > 0; o >>= 1) s += __shfl_xor_sync(0xFFFFFFFFu, s, o);
    if (lane == 0) g_rinv[w] = rsqrtf(s);
}

// ------------------------------------- edge pass 1: cosine + scatter (warp/edge)
__global__ void edge_cos_scatter_kernel(const float* __restrict__ x,
                                        const int* __restrict__ ei, int E) {
    int e    = (blockIdx.x * blockDim.x + threadIdx.x) >> 5;
    int lane = threadIdx.x & 31;
    if (e >= E) return;
    int r = ei[e];
    int c = ei[E + e];
    const float4* X = reinterpret_cast<const float4*>(x);
    float4 a = X[(size_t)r * D4 + lane];
    float4 b = X[(size_t)c * D4 + lane];
    float s = a.x * b.x + a.y * b.y + a.z * b.z + a.w * b.w;
    #pragma unroll
    for (int o = 16; o > 0; o >>= 1) s += __shfl_xor_sync(0xFFFFFFFFu, s, o);
    if (lane == 0) {
        s *= g_rinv[r] * g_rinv[c];
        atomicAdd(&g_csum[c], s);
        atomicAdd(&g_deg[c], 1);
    }
}

// --------------------- per-node: masks -> x_new, new inverse norm (warp/node)
__global__ void node_prompt_kernel(const float* __restrict__ x,
                                   const float* __restrict__ ps,
                                   const float* __restrict__ pd,
                                   const float* __restrict__ po,
                                   float* __restrict__ out, int n) {
    int w    = (blockIdx.x * blockDim.x + threadIdx.x) >> 5;
    int lane = threadIdx.x & 31;
    if (w >= n) return;

    float cs = g_csum[w];
    int   dg = g_deg[w];

    bool msim = (dg > 0) && ((cs / (float)dg) <= SIM_THR);
    bool mdeg = ((float)dg <= DEG_THR);
    bool moth = !(msim || mdeg);

    int plen = (msim && g_nz[0]) + (mdeg && g_nz[1]) + (moth && g_nz[2]);
    float inv = (plen > 0) ? (1.0f / (float)plen) : 0.0f;

    float4 xv = reinterpret_cast<const float4*>(x)[w * D4 + lane];
    float4 acc = make_float4(0.f, 0.f, 0.f, 0.f);
    if (msim) {
        float4 p = reinterpret_cast<const float4*>(ps)[lane];
        acc.x += p.x; acc.y += p.y; acc.z += p.z; acc.w += p.w;
    }
    if (mdeg) {
        float4 p = reinterpret_cast<const float4*>(pd)[lane];
        acc.x += p.x; acc.y += p.y; acc.z += p.z; acc.w += p.w;
    }
    if (moth) {
        float4 p = reinterpret_cast<const float4*>(po)[lane];
        acc.x += p.x; acc.y += p.y; acc.z += p.z; acc.w += p.w;
    }
    xv.x += acc.x * inv; xv.y += acc.y * inv;
    xv.z += acc.z * inv; xv.w += acc.w * inv;

    reinterpret_cast<float4*>(out)[w * D4 + lane] = xv;

    float s = xv.x * xv.x + xv.y * xv.y + xv.z * xv.z + xv.w * xv.w;
    #pragma unroll
    for (int o = 16; o > 0; o >>= 1) s += __shfl_xor_sync(0xFFFFFFFFu, s, o);
    if (lane == 0) {
        float nr = fmaxf(sqrtf(s), EPSV);
        g_rinv2[w] = 1.0f / nr;
    }
}

// ------------------------------- edge pass 2: cosine(x_new) -> keep (warp/edge)
__global__ void edge_keep_kernel(const float* __restrict__ xn,
                                 const int* __restrict__ ei,
                                 float* __restrict__ keep, int E) {
    int e    = (blockIdx.x * blockDim.x + threadIdx.x) >> 5;
    int lane = threadIdx.x & 31;
    if (e >= E) return;
    int r = ei[e];
    int c = ei[E + e];
    const float4* X = reinterpret_cast<const float4*>(xn);
    float4 a = X[(size_t)r * D4 + lane];
    float4 b = X[(size_t)c * D4 + lane];
    float s = a.x * b.x + a.y * b.y + a.z * b.z + a.w * b.w;
    #pragma unroll
    for (int o = 16; o > 0; o >>= 1) s += __shfl_xor_sync(0xFFFFFFFFu, s, o);
    if (lane == 0) {
        float cosv = s * g_rinv2[r] * g_rinv2[c];
        keep[e] = (cosv >= PT_THR) ? 1.0f : 0.0f;
    }
}

extern "C" void kernel_launch(void* const* d_in, const int* in_sizes, int n_in,
                              void* d_out, int out_size) {
    const float* x  = (const float*)d_in[0];
    const int*   ei = (const int*)d_in[1];
    const float* ps = (const float*)d_in[2];
    const float* pd = (const float*)d_in[3];
    const float* po = (const float*)d_in[4];
    float* out = (float*)d_out;

    int N = in_sizes[0] / D;
    int E = in_sizes[1] / 2;

    zero_kernel<<<(N + 255) / 256, 256>>>(N);
    flags_kernel<<<1, 32>>>(ps, pd, po);
    norm_kernel<<<(N + 7) / 8, 256>>>(x, N);
    edge_cos_scatter_kernel<<<(E + 7) / 8, 256>>>(x, ei, E);
    node_prompt_kernel<<<(N + 7) / 8, 256>>>(x, ps, pd, po, out, N);
    if ((long long)out_size >= (long long)N * D + E) {
        edge_keep_kernel<<<(E + 7) / 8, 256>>>(out, ei, out + (size_t)N * D, E);
    }
}

// round 2
// speedup vs baseline: 2.3125x; 2.3125x over previous
#include <cuda_runtime.h>
#include <cuda_bf16.h>

// RobustPrompt_I: graph prompt + edge pruning
//  in: x[N,128] f32, edge_index[2,E] i32, p_sim[1,128], p_deg[1,128], p_other[1,128]
//  out: x_new[N,128] f32  ++  keep[E] (0/1 as f32)

#define D        128
#define D4       32
#define NCAP     131072
#define ECAP     1048576
#define SIM_THR  0.2f
#define DEG_THR  3.0f
#define PT_THR   0.1f
#define EPSV     1e-8f

__device__ float g_csum[NCAP];    // per-node sum of edge cosines
__device__ int   g_deg[NCAP];     // per-node degree
__device__ float g_rinv[NCAP];    // 1/||x_i||
__device__ float g_dot[ECAP];     // raw dot(x_r, x_c) per edge
__device__ float4 g_A[NCAP];      // (x·p_sim, x·p_deg, x·p_other, 1/max(||x_new||,eps))
__device__ int   g_combo[NCAP];   // mask pattern idx: msim | (mdeg<<1); 0 => other
__device__ float g_W[4][4];       // combo -> weight triple over (p_sim,p_deg,p_other)
__device__ float g_GC[4][4];      // w_a^T G w_b  (delta_a · delta_b)

// ---------- setup (1 warp): nz flags, Gram, combo weights, delta-delta LUT ----------
__global__ void setup_kernel(const float* __restrict__ ps,
                             const float* __restrict__ pd,
                             const float* __restrict__ po) {
    int lane = threadIdx.x;
    float4 P[3];
    P[0] = reinterpret_cast<const float4*>(ps)[lane];
    P[1] = reinterpret_cast<const float4*>(pd)[lane];
    P[2] = reinterpret_cast<const float4*>(po)[lane];

    unsigned full = 0xFFFFFFFFu;
    int nz[3];
    #pragma unroll
    for (int k = 0; k < 3; k++) {
        bool z = (P[k].x != 0.f) & (P[k].y != 0.f) & (P[k].z != 0.f) & (P[k].w != 0.f);
        nz[k] = __all_sync(full, z);
    }
    float G[3][3];
    #pragma unroll
    for (int a = 0; a < 3; a++)
        #pragma unroll
        for (int b = 0; b < 3; b++) {
            float s = P[a].x * P[b].x + P[a].y * P[b].y + P[a].z * P[b].z + P[a].w * P[b].w;
            #pragma unroll
            for (int o = 16; o > 0; o >>= 1) s += __shfl_xor_sync(full, s, o);
            G[a][b] = s;
        }
    if (lane == 0) {
        float W[4][3];
        for (int idx = 0; idx < 4; idx++) {
            int msim = idx & 1, mdeg = (idx >> 1) & 1, moth = (idx == 0);
            float m[3] = {(float)msim, (float)mdeg, (float)moth};
            int plen = msim * nz[0] + mdeg * nz[1] + moth * nz[2];
            float inv = (plen > 0) ? (1.0f / (float)plen) : 0.0f;
            for (int k = 0; k < 3; k++) {
                W[idx][k] = m[k] * inv;
                g_W[idx][k] = W[idx][k];
            }
            g_W[idx][3] = 0.f;
        }
        for (int a = 0; a < 4; a++)
            for (int b = 0; b < 4; b++) {
                float s = 0.f;
                for (int k = 0; k < 3; k++)
                    for (int j = 0; j < 3; j++)
                        s += W[a][k] * G[k][j] * W[b][j];
                g_GC[a][b] = s;
            }
    }
}

// ---------- per-node 1/||x||, zero scratch (warp/node) ----------
__global__ void norm_kernel(const float* __restrict__ x, int n) {
    int w    = (blockIdx.x * blockDim.x + threadIdx.x) >> 5;
    int lane = threadIdx.x & 31;
    if (w >= n) return;
    float4 a = reinterpret_cast<const float4*>(x)[(size_t)w * D4 + lane];
    float s = a.x * a.x + a.y * a.y + a.z * a.z + a.w * a.w;
    #pragma unroll
    for (int o = 16; o > 0; o >>= 1) s += __shfl_xor_sync(0xFFFFFFFFu, s, o);
    if (lane == 0) {
        g_rinv[w] = rsqrtf(s);
        g_csum[w] = 0.f;
        g_deg[w]  = 0;
    }
}

// ---------- edge pass 1: raw dot + normalized scatter (8 lanes/edge) ----------
__global__ void edge1_kernel(const float* __restrict__ x,
                             const int* __restrict__ ei, int E) {
    int t   = blockIdx.x * blockDim.x + threadIdx.x;
    int e   = t >> 3;
    int sub = t & 7;
    if (e >= E) return;
    int r = __ldg(&ei[e]);
    int c = __ldg(&ei[E + e]);
    const float4* X = reinterpret_cast<const float4*>(x);
    const float4* Ar = X + (size_t)r * D4 + sub;
    const float4* Bc = X + (size_t)c * D4 + sub;
    float4 a0 = __ldg(Ar +  0), b0 = __ldg(Bc +  0);
    float4 a1 = __ldg(Ar +  8), b1 = __ldg(Bc +  8);
    float4 a2 = __ldg(Ar + 16), b2 = __ldg(Bc + 16);
    float4 a3 = __ldg(Ar + 24), b3 = __ldg(Bc + 24);
    float s = a0.x*b0.x + a0.y*b0.y + a0.z*b0.z + a0.w*b0.w;
    s += a1.x*b1.x + a1.y*b1.y + a1.z*b1.z + a1.w*b1.w;
    s += a2.x*b2.x + a2.y*b2.y + a2.z*b2.z + a2.w*b2.w;
    s += a3.x*b3.x + a3.y*b3.y + a3.z*b3.z + a3.w*b3.w;
    s += __shfl_xor_sync(0xFFFFFFFFu, s, 4);
    s += __shfl_xor_sync(0xFFFFFFFFu, s, 2);
    s += __shfl_xor_sync(0xFFFFFFFFu, s, 1);
    if (sub == 0) {
        g_dot[e] = s;
        float sn = s * g_rinv[r] * g_rinv[c];
        atomicAdd(&g_csum[c], sn);
        atomicAdd(&g_deg[c], 1);
    }
}

// ---------- node pass: masks -> x_new, prompt dots, new inv-norm (warp/node) ----------
__global__ void node_kernel(const float* __restrict__ x,
                            const float* __restrict__ ps,
                            const float* __restrict__ pd,
                            const float* __restrict__ po,
                            float* __restrict__ out, int n) {
    int w    = (blockIdx.x * blockDim.x + threadIdx.x) >> 5;
    int lane = threadIdx.x & 31;
    if (w >= n) return;

    float cs = g_csum[w];
    int   dg = g_deg[w];
    bool msim = (dg > 0) && ((cs / (float)dg) <= SIM_THR);
    bool mdeg = ((float)dg <= DEG_THR);
    int idx = (int)msim | ((int)mdeg << 1);   // 0 => other

    float4 xv = reinterpret_cast<const float4*>(x)[(size_t)w * D4 + lane];
    float4 P0 = reinterpret_cast<const float4*>(ps)[lane];
    float4 P1 = reinterpret_cast<const float4*>(pd)[lane];
    float4 P2 = reinterpret_cast<const float4*>(po)[lane];

    // prompt dots with original x (interleaved reductions)
    float d0 = xv.x*P0.x + xv.y*P0.y + xv.z*P0.z + xv.w*P0.w;
    float d1 = xv.x*P1.x + xv.y*P1.y + xv.z*P1.z + xv.w*P1.w;
    float d2 = xv.x*P2.x + xv.y*P2.y + xv.z*P2.z + xv.w*P2.w;

    // masked prompt sum / plen (bit-compatible with reference)
    bool moth = (idx == 0);
    float4 acc = make_float4(0.f, 0.f, 0.f, 0.f);
    if (msim) { acc.x += P0.x; acc.y += P0.y; acc.z += P0.z; acc.w += P0.w; }
    if (mdeg) { acc.x += P1.x; acc.y += P1.y; acc.z += P1.z; acc.w += P1.w; }
    if (moth) { acc.x += P2.x; acc.y += P2.y; acc.z += P2.z; acc.w += P2.w; }
    // plen from nz-aware weights: recover inv from g_W row sum pattern
    float w0 = g_W[idx][0], w1 = g_W[idx][1], w2 = g_W[idx][2];
    float inv = w0 + w1 + w2;                 // = plen>0 ? plen*(1/plen)=1 scaled... 
    // careful: inv must be 1/plen. w_k = mask_k/plen, so sum = (#masks)/plen.
    int nmask = (int)msim + (int)mdeg + (int)moth;
    inv = (nmask > 0) ? inv / (float)nmask : 0.0f;  // = 1/plen (or 0)

    xv.x += acc.x * inv; xv.y += acc.y * inv;
    xv.z += acc.z * inv; xv.w += acc.w * inv;
    reinterpret_cast<float4*>(out)[(size_t)w * D4 + lane] = xv;

    float s = xv.x*xv.x + xv.y*xv.y + xv.z*xv.z + xv.w*xv.w;
    #pragma unroll
    for (int o = 16; o > 0; o >>= 1) {
        s  += __shfl_xor_sync(0xFFFFFFFFu, s,  o);
        d0 += __shfl_xor_sync(0xFFFFFFFFu, d0, o);
        d1 += __shfl_xor_sync(0xFFFFFFFFu, d1, o);
        d2 += __shfl_xor_sync(0xFFFFFFFFu, d2, o);
    }
    if (lane == 0) {
        float rinv2 = 1.0f / fmaxf(sqrtf(s), EPSV);
        g_A[w] = make_float4(d0, d1, d2, rinv2);
        g_combo[w] = idx;
    }
}

// ---------- edge pass 2: decomposed cosine -> keep (thread/edge) ----------
__global__ void edge2_kernel(const int* __restrict__ ei,
                             float* __restrict__ keep, int E) {
    __shared__ float sW[4][4];
    __shared__ float sGC[4][4];
    if (threadIdx.x < 16) {
        sW[threadIdx.x >> 2][threadIdx.x & 3]  = g_W[threadIdx.x >> 2][threadIdx.x & 3];
        sGC[threadIdx.x >> 2][threadIdx.x & 3] = g_GC[threadIdx.x >> 2][threadIdx.x & 3];
    }
    __syncthreads();
    int e = blockIdx.x * blockDim.x + threadIdx.x;
    if (e >= E) return;
    int r = __ldg(&ei[e]);
    int c = __ldg(&ei[E + e]);
    float dot = g_dot[e];
    float4 Ar = g_A[r];
    float4 Ac = g_A[c];
    int cr = g_combo[r];
    int cc = g_combo[c];
    float num = dot
              + Ar.x * sW[cc][0] + Ar.y * sW[cc][1] + Ar.z * sW[cc][2]
              + Ac.x * sW[cr][0] + Ac.y * sW[cr][1] + Ac.z * sW[cr][2]
              + sGC[cr][cc];
    float cosv = num * Ar.w * Ac.w;
    keep[e] = (cosv >= PT_THR) ? 1.0f : 0.0f;
}

extern "C" void kernel_launch(void* const* d_in, const int* in_sizes, int n_in,
                              void* d_out, int out_size) {
    const float* x  = (const float*)d_in[0];
    const int*   ei = (const int*)d_in[1];
    const float* ps = (const float*)d_in[2];
    const float* pd = (const float*)d_in[3];
    const float* po = (const float*)d_in[4];
    float* out = (float*)d_out;

    int N = in_sizes[0] / D;
    int E = in_sizes[1] / 2;

    setup_kernel<<<1, 32>>>(ps, pd, po);
    norm_kernel<<<(N + 7) / 8, 256>>>(x, N);
    edge1_kernel<<<(E + 31) / 32, 256>>>(x, ei, E);
    node_kernel<<<(N + 7) / 8, 256>>>(x, ps, pd, po, out, N);
    if ((long long)out_size >= (long long)N * D + E) {
        edge2_kernel<<<(E + 255) / 256, 256>>>(ei, out + (size_t)N * D, E);
    }
}